// round 10
// baseline (speedup 1.0000x reference)
#include <cuda_runtime.h>

// ---------------------------------------------------------------------------
// GIN via linearize-before-aggregate + fixed-slot CSR gather (no float atomics)
//   y = x@W1;  w = MLP(y[n] + gather(y))@W3;  out = log_softmax(w[n]+gather(w)+b3)
// R5 structure + degree-sorted node permutation for the gather kernels:
//   k0_init, kM(proj+build), kA(hist), kB(scan), kC(place), kF1, kF2
// Gathers: 4 threads/node, float4 lanes, unroll-8 with tails (R5-exact),
// nodes processed in degree order via g_perm -> uniform warp trip counts.
// ---------------------------------------------------------------------------

#define N_NODES_MAX 50000
#define SLOTS 128            // max in-degree bound (true max ~45 for E/N=16 Poisson)

__device__ __align__(16) float g_y  [N_NODES_MAX * 16];
__device__ __align__(16) float g_w  [N_NODES_MAX * 12];
__device__ __align__(16) int   g_csr[N_NODES_MAX * SLOTS];
__device__ int g_cnt[N_NODES_MAX];
__device__ int g_perm[N_NODES_MAX];
__device__ int g_hist[64];
__device__ int g_binoff[64];
__device__ int g_idx64;

__device__ __forceinline__ void f4add(float4& a, float4 b) {
    a.x += b.x; a.y += b.y; a.z += b.z; a.w += b.w;
}

// ---------------------------------------------------------------------------
// k0: zero per-node counts + degree histogram; block 0 probes edge dtype
// ---------------------------------------------------------------------------
__global__ void k0_init(const int* __restrict__ ei_words, int N) {
    int gid = blockIdx.x * blockDim.x + threadIdx.x;
    if (gid < N) g_cnt[gid] = 0;
    if (gid < 64) g_hist[gid] = 0;
    if (blockIdx.x == 0 && threadIdx.x < 32) {
        int t = threadIdx.x;
        int v = ei_words[2 * t + 1] | ei_words[64 + 2 * t + 1];
        unsigned any = __ballot_sync(0xffffffffu, v != 0);
        if (t == 0) g_idx64 = (any == 0u) ? 1 : 0;
    }
}

// ---------------------------------------------------------------------------
// kM: merged grid. First N*16 threads: y = x@W1 (16 thr/node, broadcast smem,
// conflict-free). Remaining E threads: CSR build (int atomic rank + store).
// ---------------------------------------------------------------------------
__global__ void kM_proj_build(const float* __restrict__ x,
                              const float* __restrict__ W1,
                              const void* __restrict__ ei, int N, int E) {
    __shared__ float sW[64 * 16];
    int PROJ = N * 16;
    bool projBlock = (blockIdx.x * blockDim.x) < (unsigned)PROJ;
    if (projBlock) {
        for (int i = threadIdx.x; i < 64 * 16; i += blockDim.x) sW[i] = W1[i];
        __syncthreads();
    }
    int gid = blockIdx.x * blockDim.x + threadIdx.x;
    if (gid < PROJ) {
        int n = gid >> 4;
        int j = gid & 15;
        const float4* x4 = (const float4*)x + n * 16;
        float acc = 0.0f;
        #pragma unroll
        for (int q = 0; q < 16; q++) {
            float4 xv = x4[q];
            int k = 4 * q;
            acc += xv.x * sW[(k + 0) * 16 + j];
            acc += xv.y * sW[(k + 1) * 16 + j];
            acc += xv.z * sW[(k + 2) * 16 + j];
            acc += xv.w * sW[(k + 3) * 16 + j];
        }
        g_y[gid] = acc;
    } else {
        int e = gid - PROJ;
        if (e < E) {
            int src, dst;
            if (g_idx64) {
                const long long* p = (const long long*)ei;
                src = (int)p[e];
                dst = (int)p[E + e];
            } else {
                const int* p = (const int*)ei;
                src = p[e];
                dst = p[E + e];
            }
            int rank = atomicAdd(&g_cnt[dst], 1);
            if (rank < SLOTS) g_csr[dst * SLOTS + rank] = src;
        }
    }
}

// ---------------------------------------------------------------------------
// kA/kB/kC: counting sort of node ids by degree (64 bins)
// ---------------------------------------------------------------------------
__global__ void kA_hist(int N) {
    int n = blockIdx.x * blockDim.x + threadIdx.x;
    if (n >= N) return;
    atomicAdd(&g_hist[min(g_cnt[n], 63)], 1);
}

__global__ void kB_scan() {
    if (threadIdx.x == 0) {
        int s = 0;
        #pragma unroll
        for (int b = 0; b < 64; b++) { g_binoff[b] = s; s += g_hist[b]; }
    }
}

__global__ void kC_place(int N) {
    int n = blockIdx.x * blockDim.x + threadIdx.x;
    if (n >= N) return;
    int pos = atomicAdd(&g_binoff[min(g_cnt[n], 63)], 1);
    g_perm[pos] = n;
}

// ---------------------------------------------------------------------------
// kF1: fused gather(16) + MLP + W3 projection. 4 threads/node, lane c owns
// float4 column c; nodes visited in degree order (g_perm). Unroll x8 + tails.
// smem strides 17/11 -> lane banks conflict-free for 4-lane groups.
// ---------------------------------------------------------------------------
__global__ void kF1_gather_mlp(const float* __restrict__ b1, const float* __restrict__ W2,
                               const float* __restrict__ b2, const float* __restrict__ gamma,
                               const float* __restrict__ beta, const float* __restrict__ mean,
                               const float* __restrict__ var, const float* __restrict__ W3,
                               int N) {
    __shared__ float sS[16], sB1[16], sB2[16], sW2[16 * 17], sW3[16 * 11];
    int tid = threadIdx.x;
    if (tid < 16) {
        float s = gamma[tid] * rsqrtf(var[tid] + 1e-5f);
        sS[tid]  = s;
        sB1[tid] = b1[tid];
        sB2[tid] = (b2[tid] - mean[tid]) * s + beta[tid];
    }
    __syncthreads();
    for (int i = tid; i < 256; i += blockDim.x) {
        int k = i >> 4, j = i & 15;
        sW2[k * 17 + j] = W2[i] * sS[j];
    }
    for (int i = tid; i < 160; i += blockDim.x) {
        int k = i / 10, j = i - 10 * k;
        sW3[k * 11 + j] = W3[i];
    }
    __syncthreads();

    int gid = blockIdx.x * blockDim.x + tid;
    int g = gid >> 2;
    int c = gid & 3;
    if (g >= N) return;
    int n = g_perm[g];

    const float4* y4 = (const float4*)g_y;
    float4 acc = y4[n * 4 + c];                 // self term
    int cnt = min(g_cnt[n], SLOTS);
    const int* lst = g_csr + n * SLOTS;

    int r = 0;
    for (; r + 8 <= cnt; r += 8) {
        int4 s0 = *(const int4*)(lst + r);
        int4 s1 = *(const int4*)(lst + r + 4);
        float4 a0 = y4[s0.x * 4 + c];
        float4 a1 = y4[s0.y * 4 + c];
        float4 a2 = y4[s0.z * 4 + c];
        float4 a3 = y4[s0.w * 4 + c];
        float4 a4 = y4[s1.x * 4 + c];
        float4 a5 = y4[s1.y * 4 + c];
        float4 a6 = y4[s1.z * 4 + c];
        float4 a7 = y4[s1.w * 4 + c];
        f4add(acc, a0); f4add(acc, a1); f4add(acc, a2); f4add(acc, a3);
        f4add(acc, a4); f4add(acc, a5); f4add(acc, a6); f4add(acc, a7);
    }
    if (r + 4 <= cnt) {
        int4 s = *(const int4*)(lst + r);
        float4 a0 = y4[s.x * 4 + c];
        float4 a1 = y4[s.y * 4 + c];
        float4 a2 = y4[s.z * 4 + c];
        float4 a3 = y4[s.w * 4 + c];
        f4add(acc, a0); f4add(acc, a1); f4add(acc, a2); f4add(acc, a3);
        r += 4;
    }
    for (; r < cnt; r++) f4add(acc, y4[lst[r] * 4 + c]);

    // ---- MLP ----
    int kb = 4 * c;
    float h0 = fmaxf(acc.x + sB1[kb + 0], 0.0f);
    float h1 = fmaxf(acc.y + sB1[kb + 1], 0.0f);
    float h2 = fmaxf(acc.z + sB1[kb + 2], 0.0f);
    float h3 = fmaxf(acc.w + sB1[kb + 3], 0.0f);

    float t[16];
    #pragma unroll
    for (int j = 0; j < 16; j++) {
        t[j] = h0 * sW2[(kb + 0) * 17 + j]
             + h1 * sW2[(kb + 1) * 17 + j]
             + h2 * sW2[(kb + 2) * 17 + j]
             + h3 * sW2[(kb + 3) * 17 + j];
    }
    #pragma unroll
    for (int j = 0; j < 16; j++) {
        t[j] += __shfl_xor_sync(0xffffffffu, t[j], 1, 4);
        t[j] += __shfl_xor_sync(0xffffffffu, t[j], 2, 4);
        t[j] = fmaxf(t[j] + sB2[j], 0.0f);
    }

    float w[10];
    #pragma unroll
    for (int j = 0; j < 10; j++) {
        w[j] = t[kb + 0] * sW3[(kb + 0) * 11 + j]
             + t[kb + 1] * sW3[(kb + 1) * 11 + j]
             + t[kb + 2] * sW3[(kb + 2) * 11 + j]
             + t[kb + 3] * sW3[(kb + 3) * 11 + j];
        w[j] += __shfl_xor_sync(0xffffffffu, w[j], 1, 4);
        w[j] += __shfl_xor_sync(0xffffffffu, w[j], 2, 4);
    }

    if (c < 3) {
        float4 out;
        if (c == 0)      out = make_float4(w[0], w[1], w[2], w[3]);
        else if (c == 1) out = make_float4(w[4], w[5], w[6], w[7]);
        else             out = make_float4(w[8], w[9], 0.0f, 0.0f);
        ((float4*)g_w)[n * 3 + c] = out;
    }
}

// ---------------------------------------------------------------------------
// kF2: fused gather(12) + log_softmax, degree-ordered. 4 threads/node; lanes
// 0-2 gather their float4 column (unroll x8); lane 0 computes lsm, writes.
// ---------------------------------------------------------------------------
__global__ void kF2_gather_lsm(const float* __restrict__ b3,
                               float* __restrict__ out, int N) {
    int gid = blockIdx.x * blockDim.x + threadIdx.x;
    int g = gid >> 2;
    int c = gid & 3;
    if (g >= N) return;
    int n = g_perm[g];

    const float4* w4 = (const float4*)g_w;
    float4 acc = make_float4(0.0f, 0.0f, 0.0f, 0.0f);
    int cnt = min(g_cnt[n], SLOTS);
    const int* lst = g_csr + n * SLOTS;

    if (c < 3) {
        acc = w4[n * 3 + c];                    // self term
        int r = 0;
        for (; r + 8 <= cnt; r += 8) {
            int4 s0 = *(const int4*)(lst + r);
            int4 s1 = *(const int4*)(lst + r + 4);
            float4 a0 = w4[s0.x * 3 + c];
            float4 a1 = w4[s0.y * 3 + c];
            float4 a2 = w4[s0.z * 3 + c];
            float4 a3 = w4[s0.w * 3 + c];
            float4 a4 = w4[s1.x * 3 + c];
            float4 a5 = w4[s1.y * 3 + c];
            float4 a6 = w4[s1.z * 3 + c];
            float4 a7 = w4[s1.w * 3 + c];
            f4add(acc, a0); f4add(acc, a1); f4add(acc, a2); f4add(acc, a3);
            f4add(acc, a4); f4add(acc, a5); f4add(acc, a6); f4add(acc, a7);
        }
        if (r + 4 <= cnt) {
            int4 s = *(const int4*)(lst + r);
            float4 a0 = w4[s.x * 3 + c];
            float4 a1 = w4[s.y * 3 + c];
            float4 a2 = w4[s.z * 3 + c];
            float4 a3 = w4[s.w * 3 + c];
            f4add(acc, a0); f4add(acc, a1); f4add(acc, a2); f4add(acc, a3);
            r += 4;
        }
        for (; r < cnt; r++) f4add(acc, w4[lst[r] * 3 + c]);
    }

    // collect 10 logits at lane 0 of each 4-lane group
    float v4x = __shfl_sync(0xffffffffu, acc.x, 1, 4);
    float v5  = __shfl_sync(0xffffffffu, acc.y, 1, 4);
    float v6  = __shfl_sync(0xffffffffu, acc.z, 1, 4);
    float v7  = __shfl_sync(0xffffffffu, acc.w, 1, 4);
    float v8  = __shfl_sync(0xffffffffu, acc.x, 2, 4);
    float v9  = __shfl_sync(0xffffffffu, acc.y, 2, 4);

    if (c == 0) {
        float v[10];
        v[0] = acc.x + __ldg(&b3[0]);
        v[1] = acc.y + __ldg(&b3[1]);
        v[2] = acc.z + __ldg(&b3[2]);
        v[3] = acc.w + __ldg(&b3[3]);
        v[4] = v4x   + __ldg(&b3[4]);
        v[5] = v5    + __ldg(&b3[5]);
        v[6] = v6    + __ldg(&b3[6]);
        v[7] = v7    + __ldg(&b3[7]);
        v[8] = v8    + __ldg(&b3[8]);
        v[9] = v9    + __ldg(&b3[9]);

        float m = v[0];
        #pragma unroll
        for (int j = 1; j < 10; j++) m = fmaxf(m, v[j]);
        float s = 0.0f;
        #pragma unroll
        for (int j = 0; j < 10; j++) s += expf(v[j] - m);
        float lse = m + logf(s);

        float2* o2 = (float2*)(out + n * 10);   // 40B rows -> 8B aligned
        #pragma unroll
        for (int q = 0; q < 5; q++)
            o2[q] = make_float2(v[2 * q] - lse, v[2 * q + 1] - lse);
    }
}

// ---------------------------------------------------------------------------
extern "C" void kernel_launch(void* const* d_in, const int* in_sizes, int n_in,
                              void* d_out, int out_size) {
    const float* x     = (const float*)d_in[0];
    const void*  ei    = d_in[1];
    const float* W1    = (const float*)d_in[2];
    const float* b1    = (const float*)d_in[3];
    const float* W2    = (const float*)d_in[4];
    const float* b2    = (const float*)d_in[5];
    const float* gamma = (const float*)d_in[6];
    const float* beta  = (const float*)d_in[7];
    const float* mean  = (const float*)d_in[8];
    const float* var   = (const float*)d_in[9];
    const float* W3    = (const float*)d_in[10];
    const float* b3    = (const float*)d_in[11];

    int N = in_sizes[0] / 64;   // 50000
    int E = in_sizes[1] / 2;    // 800000

    k0_init<<<(N + 255) / 256, 256>>>((const int*)ei, N);
    kM_proj_build<<<(N * 16 + E + 255) / 256, 256>>>(x, W1, ei, N, E);
    kA_hist<<<(N + 255) / 256, 256>>>(N);
    kB_scan<<<1, 32>>>();
    kC_place<<<(N + 255) / 256, 256>>>(N);
    kF1_gather_mlp<<<(N * 4 + 255) / 256, 256>>>(b1, W2, b2, gamma, beta, mean, var, W3, N);
    kF2_gather_lsm<<<(N * 4 + 255) / 256, 256>>>(b3, (float*)d_out, N);
}

// round 12
// speedup vs baseline: 1.6598x; 1.6598x over previous
#include <cuda_runtime.h>

// ---------------------------------------------------------------------------
// GIN via linearize-before-aggregate + fixed-slot CSR gather (no float atomics)
//   y = x@W1;  w = MLP(y[n] + gather(y))@W3;  out = log_softmax(w[n]+gather(w)+b3)
// 4 launches (R5 structure, proven 51.2us): k0_init, kM(proj+build),
//   kF1(gather16+MLP), kF2(gather12+lsm).
// Single change vs R5: kM projection stages x rows in smem (kills the 16x
// global load amplification; smem reads are broadcast conflict-free).
// (Resubmission of R11 — R11 bench was an infra failure, not a kernel one.)
// ---------------------------------------------------------------------------

#define N_NODES_MAX 50000
#define SLOTS 128            // max in-degree bound (true max ~45 for E/N=16 Poisson)

__device__ __align__(16) float g_y  [N_NODES_MAX * 16];
__device__ __align__(16) float g_w  [N_NODES_MAX * 12];
__device__ __align__(16) int   g_csr[N_NODES_MAX * SLOTS];
__device__ int g_cnt[N_NODES_MAX];
__device__ int g_idx64;

__device__ __forceinline__ void f4add(float4& a, float4 b) {
    a.x += b.x; a.y += b.y; a.z += b.z; a.w += b.w;
}

// ---------------------------------------------------------------------------
// k0: zero per-node counts; block 0 probes edge dtype (int64 -> odd words 0)
// ---------------------------------------------------------------------------
__global__ void k0_init(const int* __restrict__ ei_words, int N) {
    int gid = blockIdx.x * blockDim.x + threadIdx.x;
    if (gid < N) g_cnt[gid] = 0;
    if (blockIdx.x == 0 && threadIdx.x < 32) {
        int t = threadIdx.x;
        int v = ei_words[2 * t + 1] | ei_words[64 + 2 * t + 1];
        unsigned any = __ballot_sync(0xffffffffu, v != 0);
        if (t == 0) g_idx64 = (any == 0u) ? 1 : 0;
    }
}

// ---------------------------------------------------------------------------
// kM: merged grid. First N*16 threads: y = x@W1 (16 thr/node, x staged in
// smem: each row loaded from global ONCE, then broadcast-read). Remaining E
// threads: CSR build. N*16 % 256 == 0 -> proj/edge blocks never straddle.
// ---------------------------------------------------------------------------
__global__ void kM_proj_build(const float* __restrict__ x,
                              const float* __restrict__ W1,
                              const void* __restrict__ ei, int N, int E) {
    __shared__ float sW[64 * 16];
    __shared__ float4 sX[16 * 16];   // 16 nodes x 16 float4 (64 floats)
    int PROJ = N * 16;
    int gid = blockIdx.x * blockDim.x + threadIdx.x;
    bool projBlock = (blockIdx.x * blockDim.x) < (unsigned)PROJ;
    if (projBlock) {
        for (int i = threadIdx.x; i < 64 * 16; i += blockDim.x) sW[i] = W1[i];
        // stage this block's 16 x rows (coalesced: 256 float4 = 4KB)
        int nodeBase = (blockIdx.x * blockDim.x) >> 4;   // first node of block
        int rows = min(16, N - nodeBase);
        const float4* xg = (const float4*)x + nodeBase * 16;
        if (threadIdx.x < rows * 16) sX[threadIdx.x] = xg[threadIdx.x];
        __syncthreads();
    }
    if (gid < PROJ) {
        int j  = gid & 15;
        int ln = (threadIdx.x >> 4);          // node index within block
        const float4* xr = sX + ln * 16;
        float acc = 0.0f;
        #pragma unroll
        for (int q = 0; q < 16; q++) {
            float4 xv = xr[q];
            int k = 4 * q;
            acc += xv.x * sW[(k + 0) * 16 + j];
            acc += xv.y * sW[(k + 1) * 16 + j];
            acc += xv.z * sW[(k + 2) * 16 + j];
            acc += xv.w * sW[(k + 3) * 16 + j];
        }
        g_y[gid] = acc;
    } else {
        int e = gid - PROJ;
        if (e < E) {
            int src, dst;
            if (g_idx64) {
                const long long* p = (const long long*)ei;
                src = (int)p[e];
                dst = (int)p[E + e];
            } else {
                const int* p = (const int*)ei;
                src = p[e];
                dst = p[E + e];
            }
            int rank = atomicAdd(&g_cnt[dst], 1);
            if (rank < SLOTS) g_csr[dst * SLOTS + rank] = src;
        }
    }
}

// ---------------------------------------------------------------------------
// kF1: fused gather(16) + MLP + W3 projection. 4 threads/node, lane c owns
// float4 column c. Neighbor loop unrolled x8 (R5-exact).
// smem strides 17/11 -> lane banks conflict-free for 4-lane groups.
// ---------------------------------------------------------------------------
__global__ void kF1_gather_mlp(const float* __restrict__ b1, const float* __restrict__ W2,
                               const float* __restrict__ b2, const float* __restrict__ gamma,
                               const float* __restrict__ beta, const float* __restrict__ mean,
                               const float* __restrict__ var, const float* __restrict__ W3,
                               int N) {
    __shared__ float sS[16], sB1[16], sB2[16], sW2[16 * 17], sW3[16 * 11];
    int tid = threadIdx.x;
    if (tid < 16) {
        float s = gamma[tid] * rsqrtf(var[tid] + 1e-5f);
        sS[tid]  = s;
        sB1[tid] = b1[tid];
        sB2[tid] = (b2[tid] - mean[tid]) * s + beta[tid];
    }
    __syncthreads();
    for (int i = tid; i < 256; i += blockDim.x) {
        int k = i >> 4, j = i & 15;
        sW2[k * 17 + j] = W2[i] * sS[j];
    }
    for (int i = tid; i < 160; i += blockDim.x) {
        int k = i / 10, j = i - 10 * k;
        sW3[k * 11 + j] = W3[i];
    }
    __syncthreads();

    int gid = blockIdx.x * blockDim.x + tid;
    int n = gid >> 2;
    int c = gid & 3;
    if (n >= N) return;

    const float4* y4 = (const float4*)g_y;
    float4 acc = y4[n * 4 + c];                 // self term
    int cnt = min(g_cnt[n], SLOTS);
    const int* lst = g_csr + n * SLOTS;

    int r = 0;
    for (; r + 8 <= cnt; r += 8) {
        int4 s0 = *(const int4*)(lst + r);
        int4 s1 = *(const int4*)(lst + r + 4);
        float4 a0 = y4[s0.x * 4 + c];
        float4 a1 = y4[s0.y * 4 + c];
        float4 a2 = y4[s0.z * 4 + c];
        float4 a3 = y4[s0.w * 4 + c];
        float4 a4 = y4[s1.x * 4 + c];
        float4 a5 = y4[s1.y * 4 + c];
        float4 a6 = y4[s1.z * 4 + c];
        float4 a7 = y4[s1.w * 4 + c];
        f4add(acc, a0); f4add(acc, a1); f4add(acc, a2); f4add(acc, a3);
        f4add(acc, a4); f4add(acc, a5); f4add(acc, a6); f4add(acc, a7);
    }
    if (r + 4 <= cnt) {
        int4 s = *(const int4*)(lst + r);
        float4 a0 = y4[s.x * 4 + c];
        float4 a1 = y4[s.y * 4 + c];
        float4 a2 = y4[s.z * 4 + c];
        float4 a3 = y4[s.w * 4 + c];
        f4add(acc, a0); f4add(acc, a1); f4add(acc, a2); f4add(acc, a3);
        r += 4;
    }
    for (; r < cnt; r++) f4add(acc, y4[lst[r] * 4 + c]);

    // ---- MLP ----
    int kb = 4 * c;
    float h0 = fmaxf(acc.x + sB1[kb + 0], 0.0f);
    float h1 = fmaxf(acc.y + sB1[kb + 1], 0.0f);
    float h2 = fmaxf(acc.z + sB1[kb + 2], 0.0f);
    float h3 = fmaxf(acc.w + sB1[kb + 3], 0.0f);

    float t[16];
    #pragma unroll
    for (int j = 0; j < 16; j++) {
        t[j] = h0 * sW2[(kb + 0) * 17 + j]
             + h1 * sW2[(kb + 1) * 17 + j]
             + h2 * sW2[(kb + 2) * 17 + j]
             + h3 * sW2[(kb + 3) * 17 + j];
    }
    #pragma unroll
    for (int j = 0; j < 16; j++) {
        t[j] += __shfl_xor_sync(0xffffffffu, t[j], 1, 4);
        t[j] += __shfl_xor_sync(0xffffffffu, t[j], 2, 4);
        t[j] = fmaxf(t[j] + sB2[j], 0.0f);
    }

    float w[10];
    #pragma unroll
    for (int j = 0; j < 10; j++) {
        w[j] = t[kb + 0] * sW3[(kb + 0) * 11 + j]
             + t[kb + 1] * sW3[(kb + 1) * 11 + j]
             + t[kb + 2] * sW3[(kb + 2) * 11 + j]
             + t[kb + 3] * sW3[(kb + 3) * 11 + j];
        w[j] += __shfl_xor_sync(0xffffffffu, w[j], 1, 4);
        w[j] += __shfl_xor_sync(0xffffffffu, w[j], 2, 4);
    }

    if (c < 3) {
        float4 out;
        if (c == 0)      out = make_float4(w[0], w[1], w[2], w[3]);
        else if (c == 1) out = make_float4(w[4], w[5], w[6], w[7]);
        else             out = make_float4(w[8], w[9], 0.0f, 0.0f);
        ((float4*)g_w)[n * 3 + c] = out;
    }
}

// ---------------------------------------------------------------------------
// kF2: fused gather(12) + log_softmax. 4 threads/node; lanes 0-2 gather their
// float4 column (unroll x8); lane 0 collects via shuffles, computes lsm, writes.
// ---------------------------------------------------------------------------
__global__ void kF2_gather_lsm(const float* __restrict__ b3,
                               float* __restrict__ out, int N) {
    int gid = blockIdx.x * blockDim.x + threadIdx.x;
    int n = gid >> 2;
    int c = gid & 3;
    if (n >= N) return;

    const float4* w4 = (const float4*)g_w;
    float4 acc = make_float4(0.0f, 0.0f, 0.0f, 0.0f);
    int cnt = min(g_cnt[n], SLOTS);
    const int* lst = g_csr + n * SLOTS;

    if (c < 3) {
        acc = w4[n * 3 + c];                    // self term
        int r = 0;
        for (; r + 8 <= cnt; r += 8) {
            int4 s0 = *(const int4*)(lst + r);
            int4 s1 = *(const int4*)(lst + r + 4);
            float4 a0 = w4[s0.x * 3 + c];
            float4 a1 = w4[s0.y * 3 + c];
            float4 a2 = w4[s0.z * 3 + c];
            float4 a3 = w4[s0.w * 3 + c];
            float4 a4 = w4[s1.x * 3 + c];
            float4 a5 = w4[s1.y * 3 + c];
            float4 a6 = w4[s1.z * 3 + c];
            float4 a7 = w4[s1.w * 3 + c];
            f4add(acc, a0); f4add(acc, a1); f4add(acc, a2); f4add(acc, a3);
            f4add(acc, a4); f4add(acc, a5); f4add(acc, a6); f4add(acc, a7);
        }
        if (r + 4 <= cnt) {
            int4 s = *(const int4*)(lst + r);
            float4 a0 = w4[s.x * 3 + c];
            float4 a1 = w4[s.y * 3 + c];
            float4 a2 = w4[s.z * 3 + c];
            float4 a3 = w4[s.w * 3 + c];
            f4add(acc, a0); f4add(acc, a1); f4add(acc, a2); f4add(acc, a3);
            r += 4;
        }
        for (; r < cnt; r++) f4add(acc, w4[lst[r] * 3 + c]);
    }

    // collect 10 logits at lane 0 of each 4-lane group
    float v4x = __shfl_sync(0xffffffffu, acc.x, 1, 4);
    float v5  = __shfl_sync(0xffffffffu, acc.y, 1, 4);
    float v6  = __shfl_sync(0xffffffffu, acc.z, 1, 4);
    float v7  = __shfl_sync(0xffffffffu, acc.w, 1, 4);
    float v8  = __shfl_sync(0xffffffffu, acc.x, 2, 4);
    float v9  = __shfl_sync(0xffffffffu, acc.y, 2, 4);

    if (c == 0) {
        float v[10];
        v[0] = acc.x + __ldg(&b3[0]);
        v[1] = acc.y + __ldg(&b3[1]);
        v[2] = acc.z + __ldg(&b3[2]);
        v[3] = acc.w + __ldg(&b3[3]);
        v[4] = v4x   + __ldg(&b3[4]);
        v[5] = v5    + __ldg(&b3[5]);
        v[6] = v6    + __ldg(&b3[6]);
        v[7] = v7    + __ldg(&b3[7]);
        v[8] = v8    + __ldg(&b3[8]);
        v[9] = v9    + __ldg(&b3[9]);

        float m = v[0];
        #pragma unroll
        for (int j = 1; j < 10; j++) m = fmaxf(m, v[j]);
        float s = 0.0f;
        #pragma unroll
        for (int j = 0; j < 10; j++) s += expf(v[j] - m);
        float lse = m + logf(s);

        float2* o2 = (float2*)(out + n * 10);   // 40B rows -> 8B aligned
        #pragma unroll
        for (int q = 0; q < 5; q++)
            o2[q] = make_float2(v[2 * q] - lse, v[2 * q + 1] - lse);
    }
}

// ---------------------------------------------------------------------------
extern "C" void kernel_launch(void* const* d_in, const int* in_sizes, int n_in,
                              void* d_out, int out_size) {
    const float* x     = (const float*)d_in[0];
    const void*  ei    = d_in[1];
    const float* W1    = (const float*)d_in[2];
    const float* b1    = (const float*)d_in[3];
    const float* W2    = (const float*)d_in[4];
    const float* b2    = (const float*)d_in[5];
    const float* gamma = (const float*)d_in[6];
    const float* beta  = (const float*)d_in[7];
    const float* mean  = (const float*)d_in[8];
    const float* var   = (const float*)d_in[9];
    const float* W3    = (const float*)d_in[10];
    const float* b3    = (const float*)d_in[11];

    int N = in_sizes[0] / 64;   // 50000
    int E = in_sizes[1] / 2;    // 800000

    k0_init<<<(N + 255) / 256, 256>>>((const int*)ei, N);
    kM_proj_build<<<(N * 16 + E + 255) / 256, 256>>>(x, W1, ei, N, E);
    kF1_gather_mlp<<<(N * 4 + 255) / 256, 256>>>(b1, W2, b2, gamma, beta, mean, var, W3, N);
    kF2_gather_lsm<<<(N * 4 + 255) / 256, 256>>>(b3, (float*)d_out, N);
}